// round 14
// baseline (speedup 1.0000x reference)
#include <cuda_runtime.h>
#include <math_constants.h>

// StratifiedMaxPooling: out[b,c] = max_{j: labels[j]==c} values[b,j]
// values: [B=128, N=200000] f32, labels: [N] int32, C=100.
//
// R14 = R8 config (296 blocks, 2 CTA/SM, TILE=64) with a restructured
// inner loop:
//  - 4-column batches; ALL loads (class via broadcast LDS — no SHFL,
//    8 stage LDS, 8 acc LDS) issued before ANY store => compiler can't be
//    forced to serialize on may-alias acc RMWs; deep LDS MLP.
//  - duplicate classes inside a batch folded in registers (6 predicated
//    pairwise folds) so the trailing 8 STS are correct under aliasing:
//    last STS per class carries all earlier maxes. Mask-empty repeats are
//    idempotent (same column).
//  - Cross-iteration same-class RMWs are same-warp/lane program-ordered.
// Everything else identical to R8 (best passing: 41.5us).

#define FULL 0xFFFFFFFFu

static const int NTHR    = 512;    // 16 warps
static const int ROWS_PB = 64;     // rows per block
static const int C_NUM   = 100;
static const int C_PAD   = 101;    // acc pitch
static const int NOUT    = 128 * C_NUM;   // 12800
static const int TILE    = 64;     // columns per tile
static const int RPITCH  = 65;     // stage row pitch
static const int NSTREAM = 148;    // tile stride (grid = 2*NSTREAM)

__device__ unsigned g_keys[NOUT];  // zero static init; self-cleaning
__device__ unsigned g_done;        // zero static init; self-cleaning

__device__ __forceinline__ unsigned ukey(float f) {
    int x = __float_as_int(f);
    return (unsigned)(x ^ ((x >> 31) | 0x80000000));
}
__device__ __forceinline__ float udecode(unsigned u) {
    unsigned m = ((int)u < 0) ? 0x80000000u : 0xFFFFFFFFu;
    return __int_as_float((int)(u ^ m));
}

__global__ __launch_bounds__(NTHR, 2)
void pool_kernel(const float* __restrict__ values,
                 const int*   __restrict__ labels,
                 float* __restrict__ out, int N, int ntiles)
{
    __shared__ float stage[2][TILE * RPITCH];  // 2 x 16.6 KB
    __shared__ int   scl[2][TILE];
    __shared__ float acc[ROWS_PB * C_PAD];     // 25.9 KB
    __shared__ int   s_last;

    const int tid  = threadIdx.x;
    const int lane = tid & 31;
    const int warp = tid >> 5;                 // column group id (0..15)
    const int half = blockIdx.x & 1;
    const int strm = blockIdx.x >> 1;

    for (int i = tid; i < ROWS_PB * C_PAD; i += NTHR) acc[i] = -CUDART_INF_F;

    // ---- load mapping: thread -> row (tid>>3), two 4-col quads (q, q+8)
    const int lrow = tid >> 3;
    const int q    = tid & 7;
    const float* const vrow = values + (size_t)(half * ROWS_PB + lrow) * N;
    const int cqa = 4 * q;
    const int cqb = 4 * (q + 8);
    const int sofa = cqa * RPITCH + lrow;
    const int sofb = cqb * RPITCH + lrow;

    // ---- process mapping
    float* const accA = acc + lane * C_PAD;
    float* const accB = acc + (lane + 32) * C_PAD;

    // ---- prologue: stage tile t0 into buf0; prefetch t0+NSTREAM into regs
    int t = strm;
    if (t < ntiles) {
        const float* vt = vrow + (size_t)t * TILE;
        float4 a = __ldcs(reinterpret_cast<const float4*>(vt + cqa));
        float4 b = __ldcs(reinterpret_cast<const float4*>(vt + cqb));
        float* sa = &stage[0][sofa];
        float* sb = &stage[0][sofb];
        sa[0] = a.x; sa[RPITCH] = a.y; sa[2*RPITCH] = a.z; sa[3*RPITCH] = a.w;
        sb[0] = b.x; sb[RPITCH] = b.y; sb[2*RPITCH] = b.z; sb[3*RPITCH] = b.w;
        if (tid < TILE) scl[0][tid] = labels[t * TILE + tid];
    }
    int    t1 = t + NSTREAM;
    bool   h1 = t1 < ntiles;
    float4 va = make_float4(0.f,0.f,0.f,0.f), vb = va;
    int    l1 = 0;
    if (h1) {
        const float* vt = vrow + (size_t)t1 * TILE;
        va = __ldcs(reinterpret_cast<const float4*>(vt + cqa));
        vb = __ldcs(reinterpret_cast<const float4*>(vt + cqb));
        if (tid < TILE) l1 = labels[t1 * TILE + tid];
    }
    __syncthreads();   // buf0 + acc ready

    int p = 0;
    for (; t < ntiles; t += NSTREAM) {
        // store prefetched tile into buf 1-p
        if (h1) {
            float* sa = &stage[1 - p][sofa];
            float* sb = &stage[1 - p][sofb];
            sa[0]=va.x; sa[RPITCH]=va.y; sa[2*RPITCH]=va.z; sa[3*RPITCH]=va.w;
            sb[0]=vb.x; sb[RPITCH]=vb.y; sb[2*RPITCH]=vb.z; sb[3*RPITCH]=vb.w;
            if (tid < TILE) scl[1 - p][tid] = l1;
        }
        // prefetch t+2*NSTREAM (overlaps processing below)
        const int t2 = t + 2 * NSTREAM;
        const bool h2 = t2 < ntiles;
        if (h2) {
            const float* vt = vrow + (size_t)t2 * TILE;
            va = __ldcs(reinterpret_cast<const float4*>(vt + cqa));
            vb = __ldcs(reinterpret_cast<const float4*>(vt + cqb));
            if (tid < TILE) l1 = labels[t2 * TILE + tid];
        }
        h1 = h2;

        // ---- process tile t from buf p: two 32-column sub-tiles
        const float* const stg = stage[p];
        const int*   const scp = scl[p];
#pragma unroll
        for (int sub = 0; sub < 2; sub++) {
            const int cls = scp[sub * 32 + lane];
            unsigned mask = __ballot_sync(FULL, (cls & 15) == warp);
            const float* const sbase = stg + (sub * 32) * RPITCH;
            const int* const scsub = scp + sub * 32;
            while (mask) {
                // extract up to 4 columns (repeats when mask drains: benign)
                const int c0 = __ffs((int)mask) - 1;     mask &= mask - 1;
                const int c1 = mask ? __ffs((int)mask)-1 : c0; mask &= mask-1;
                const int c2 = mask ? __ffs((int)mask)-1 : c1; mask &= mask-1;
                const int c3 = mask ? __ffs((int)mask)-1 : c2; mask &= mask-1;

                // classes via broadcast LDS (no SHFL)
                const int k0 = scsub[c0];
                const int k1 = scsub[c1];
                const int k2 = scsub[c2];
                const int k3 = scsub[c3];

                // stage values (8 independent LDS)
                const float* s0 = sbase + c0 * RPITCH;
                const float* s1 = sbase + c1 * RPITCH;
                const float* s2 = sbase + c2 * RPITCH;
                const float* s3 = sbase + c3 * RPITCH;
                const float x0a = s0[lane], x0b = s0[lane + 32];
                const float x1a = s1[lane], x1b = s1[lane + 32];
                const float x2a = s2[lane], x2b = s2[lane + 32];
                const float x3a = s3[lane], x3b = s3[lane + 32];

                // acc old values (8 independent LDS, before any store)
                float* const a0 = accA + k0; float* const b0 = accB + k0;
                float* const a1 = accA + k1; float* const b1 = accB + k1;
                float* const a2 = accA + k2; float* const b2 = accB + k2;
                float* const a3 = accA + k3; float* const b3 = accB + k3;
                float m0a = fmaxf(*a0, x0a), m0b = fmaxf(*b0, x0b);
                float m1a = fmaxf(*a1, x1a), m1b = fmaxf(*b1, x1b);
                float m2a = fmaxf(*a2, x2a), m2b = fmaxf(*b2, x2b);
                float m3a = fmaxf(*a3, x3a), m3b = fmaxf(*b3, x3b);

                // fold duplicate classes so the LAST store per class carries
                // all earlier maxes (stores below are program-ordered)
                if (k1 == k0) { m1a = fmaxf(m1a, m0a); m1b = fmaxf(m1b, m0b); }
                if (k2 == k0) { m2a = fmaxf(m2a, m0a); m2b = fmaxf(m2b, m0b); }
                if (k2 == k1) { m2a = fmaxf(m2a, m1a); m2b = fmaxf(m2b, m1b); }
                if (k3 == k0) { m3a = fmaxf(m3a, m0a); m3b = fmaxf(m3b, m0b); }
                if (k3 == k1) { m3a = fmaxf(m3a, m1a); m3b = fmaxf(m3b, m1b); }
                if (k3 == k2) { m3a = fmaxf(m3a, m2a); m3b = fmaxf(m3b, m2b); }

                *a0 = m0a; *b0 = m0b;
                *a1 = m1a; *b1 = m1b;
                *a2 = m2a; *b2 = m2b;
                *a3 = m3a; *b3 = m3b;
            }
        }
        __syncthreads();   // buf 1-p stores done; buf p reads done
        p ^= 1;
    }

    // ---- remainder columns (N % 64 == 0 here; kept for generality)
    const int remstart = ntiles * TILE;
    if (remstart < N && strm == 0) {
        const int rem = N - remstart;
        for (int i = tid; i < rem * ROWS_PB; i += NTHR) {
            const int r = i / rem;
            const int j = remstart + (i - r * rem);
            const int grow = half * ROWS_PB + r;
            atomicMax(&g_keys[grow * C_NUM + labels[j]],
                      ukey(values[(size_t)grow * N + j]));
        }
    }

    // ---- flush block partials (rotated start staggers same-addr atomics)
    {
        const int rot = (blockIdx.x * 1051) % (ROWS_PB * C_NUM);
        for (int i = tid; i < ROWS_PB * C_NUM; i += NTHR) {
            int i2 = i + rot;
            if (i2 >= ROWS_PB * C_NUM) i2 -= ROWS_PB * C_NUM;
            const int r = i2 / C_NUM;
            const int c = i2 - r * C_NUM;
            atomicMax(&g_keys[(half * ROWS_PB + r) * C_NUM + c],
                      ukey(acc[r * C_PAD + c]));
        }
    }
    __threadfence();
    __syncthreads();
    if (tid == 0)
        s_last = (atomicAdd(&g_done, 1u) == (unsigned)(gridDim.x - 1));
    __syncthreads();

    // ---- last block: decode to output, self-reset for graph replays
    if (s_last) {
        for (int i = tid; i < NOUT; i += NTHR) {
            out[i] = udecode(__ldcg(&g_keys[i]));
            g_keys[i] = 0u;
        }
        __threadfence();
        if (tid == 0) g_done = 0u;
    }
}

extern "C" void kernel_launch(void* const* d_in, const int* in_sizes, int n_in,
                              void* d_out, int out_size)
{
    const float* values = (const float*)d_in[0];
    const int*   labels = (const int*)d_in[1];
    const int N = in_sizes[1];        // 200000
    const int ntiles = N / TILE;      // 3125

    pool_kernel<<<2 * NSTREAM, NTHR>>>(values, labels, (float*)d_out, N, ntiles);
}

// round 15
// speedup vs baseline: 1.1375x; 1.1375x over previous
#include <cuda_runtime.h>
#include <math_constants.h>

// StratifiedMaxPooling: out[b,c] = max_{j: labels[j]==c} values[b,j]
// values: [B=128, N=200000] f32, labels: [N] int32, C=100.
//
// R15 = R8 (best: 41.5us) with ONE change: TILE 64 -> 128 (4 sub-tiles per
// barrier) to average warp load imbalance (max/mean of Binom(n,1/16) drops
// 1.84x -> 1.61x) and halve barrier count. Inner loop / grouping / pitches /
// grid identical to R8. Smem now 93.4KB/block -> all dynamic + attribute
// opt-in (2 CTAs/SM preserved: 187KB <= 228KB).

#define FULL 0xFFFFFFFFu

static const int NTHR    = 512;    // 16 warps
static const int ROWS_PB = 64;     // rows per block
static const int C_NUM   = 100;
static const int C_PAD   = 101;    // acc pitch
static const int NOUT    = 128 * C_NUM;   // 12800
static const int TILE    = 128;    // columns per tile (4 x 32 sub-tiles)
static const int RPITCH  = 65;     // stage row pitch
static const int NSTREAM = 148;    // tile stride (grid = 2*NSTREAM)
static const int STG_F   = TILE * RPITCH;      // 8320 floats per buffer
static const int ACC_F   = ROWS_PB * C_PAD;    // 6464 floats

__device__ unsigned g_keys[NOUT];  // zero static init; self-cleaning
__device__ unsigned g_done;        // zero static init; self-cleaning

__device__ __forceinline__ unsigned ukey(float f) {
    int x = __float_as_int(f);
    return (unsigned)(x ^ ((x >> 31) | 0x80000000));
}
__device__ __forceinline__ float udecode(unsigned u) {
    unsigned m = ((int)u < 0) ? 0x80000000u : 0xFFFFFFFFu;
    return __int_as_float((int)(u ^ m));
}

__global__ __launch_bounds__(NTHR, 2)
void pool_kernel(const float* __restrict__ values,
                 const int*   __restrict__ labels,
                 float* __restrict__ out, int N, int ntiles)
{
    extern __shared__ __align__(16) float sdyn[];
    float* const stage = sdyn;                         // [2][STG_F]
    float* const acc   = sdyn + 2 * STG_F;             // [row][class]
    int*   const scl   = (int*)(sdyn + 2 * STG_F + ACC_F);  // [2][TILE]
    __shared__ int s_last;

    const int tid  = threadIdx.x;
    const int lane = tid & 31;
    const int warp = tid >> 5;                 // column group id (0..15)
    const int half = blockIdx.x & 1;
    const int strm = blockIdx.x >> 1;

    for (int i = tid; i < ACC_F; i += NTHR) acc[i] = -CUDART_INF_F;

    // ---- load mapping: thread -> row (tid>>3), quads at cols 4q+32s
    const int lrow = tid >> 3;
    const int q4   = (tid & 7) * 4;
    const float* const vrow = values + (size_t)(half * ROWS_PB + lrow) * N;
    int sof[4];
#pragma unroll
    for (int s = 0; s < 4; s++) sof[s] = (q4 + 32 * s) * RPITCH + lrow;

    // ---- process mapping (identical to R8)
    float* const accA = acc + lane * C_PAD;
    float* const accB = acc + (lane + 32) * C_PAD;

    // ---- prologue: stage tile t0 into buf0; prefetch t0+NSTREAM into regs
    int t = strm;
    if (t < ntiles) {
        const float* vt = vrow + (size_t)t * TILE;
#pragma unroll
        for (int s = 0; s < 4; s++) {
            float4 v = __ldcs(reinterpret_cast<const float4*>(vt + q4 + 32 * s));
            float* sp = stage + sof[s];
            sp[0] = v.x; sp[RPITCH] = v.y;
            sp[2 * RPITCH] = v.z; sp[3 * RPITCH] = v.w;
        }
        if (tid < TILE) scl[tid] = labels[t * TILE + tid];
    }
    int    t1 = t + NSTREAM;
    bool   h1 = t1 < ntiles;
    float4 pv[4];
#pragma unroll
    for (int s = 0; s < 4; s++) pv[s] = make_float4(0.f, 0.f, 0.f, 0.f);
    int pl = 0;
    if (h1) {
        const float* vt = vrow + (size_t)t1 * TILE;
#pragma unroll
        for (int s = 0; s < 4; s++)
            pv[s] = __ldcs(reinterpret_cast<const float4*>(vt + q4 + 32 * s));
        if (tid < TILE) pl = labels[t1 * TILE + tid];
    }
    __syncthreads();   // buf0 + acc ready

    int p = 0;
    for (; t < ntiles; t += NSTREAM) {
        // store prefetched tile into buf 1-p
        if (h1) {
            float* sb = stage + (1 - p) * STG_F;
#pragma unroll
            for (int s = 0; s < 4; s++) {
                float* sp = sb + sof[s];
                sp[0] = pv[s].x; sp[RPITCH] = pv[s].y;
                sp[2 * RPITCH] = pv[s].z; sp[3 * RPITCH] = pv[s].w;
            }
            if (tid < TILE) scl[(1 - p) * TILE + tid] = pl;
        }
        // prefetch t+2*NSTREAM (overlaps processing below)
        const int t2 = t + 2 * NSTREAM;
        const bool h2 = t2 < ntiles;
        if (h2) {
            const float* vt = vrow + (size_t)t2 * TILE;
#pragma unroll
            for (int s = 0; s < 4; s++)
                pv[s] = __ldcs(reinterpret_cast<const float4*>(vt + q4 + 32 * s));
            if (tid < TILE) pl = labels[t2 * TILE + tid];
        }
        h1 = h2;

        // ---- process tile t from buf p: four 32-column sub-tiles (R8 loop)
        const float* const stg = stage + p * STG_F;
        const int*   const scp = scl + p * TILE;
#pragma unroll
        for (int sub = 0; sub < 4; sub++) {
            const int cls = scp[sub * 32 + lane];
            unsigned mask = __ballot_sync(FULL, (cls & 15) == warp);
            const float* const sbase = stg + (sub * 32) * RPITCH;
            while (mask) {
                const int c0 = __ffs((int)mask) - 1; mask &= mask - 1;
                int c1 = c0;
                if (mask) { c1 = __ffs((int)mask) - 1; mask &= mask - 1; }
                const int k0 = __shfl_sync(FULL, cls, c0);
                const int k1 = __shfl_sync(FULL, cls, c1);
                const float* s0 = sbase + c0 * RPITCH;
                const float* s1 = sbase + c1 * RPITCH;
                const float x0a = s0[lane], x0b = s0[lane + 32];
                const float x1a = s1[lane], x1b = s1[lane + 32];
                float* p0a = accA + k0;  float* p0b = accB + k0;
                float* p1a = accA + k1;  float* p1b = accB + k1;
                // c1==c0 repeat is same-lane => thread-ordered, still correct
                *p0a = fmaxf(*p0a, x0a);
                *p0b = fmaxf(*p0b, x0b);
                *p1a = fmaxf(*p1a, x1a);
                *p1b = fmaxf(*p1b, x1b);
            }
        }
        __syncthreads();   // buf 1-p stores done; buf p reads done
        p ^= 1;
    }

    // ---- remainder columns (N % 128 == 64): strm==0 blocks, global atomics
    const int remstart = ntiles * TILE;
    if (remstart < N && strm == 0) {
        const int rem = N - remstart;
        for (int i = tid; i < rem * ROWS_PB; i += NTHR) {
            const int r = i / rem;
            const int j = remstart + (i - r * rem);
            const int grow = half * ROWS_PB + r;
            atomicMax(&g_keys[grow * C_NUM + labels[j]],
                      ukey(values[(size_t)grow * N + j]));
        }
    }

    // ---- flush block partials (rotated start staggers same-addr atomics)
    {
        const int rot = (blockIdx.x * 1051) % (ROWS_PB * C_NUM);
        for (int i = tid; i < ROWS_PB * C_NUM; i += NTHR) {
            int i2 = i + rot;
            if (i2 >= ROWS_PB * C_NUM) i2 -= ROWS_PB * C_NUM;
            const int r = i2 / C_NUM;
            const int c = i2 - r * C_NUM;
            atomicMax(&g_keys[(half * ROWS_PB + r) * C_NUM + c],
                      ukey(acc[r * C_PAD + c]));
        }
    }
    __threadfence();
    __syncthreads();
    if (tid == 0)
        s_last = (atomicAdd(&g_done, 1u) == (unsigned)(gridDim.x - 1));
    __syncthreads();

    // ---- last block: decode to output, self-reset for graph replays
    if (s_last) {
        for (int i = tid; i < NOUT; i += NTHR) {
            out[i] = udecode(__ldcg(&g_keys[i]));
            g_keys[i] = 0u;
        }
        __threadfence();
        if (tid == 0) g_done = 0u;
    }
}

extern "C" void kernel_launch(void* const* d_in, const int* in_sizes, int n_in,
                              void* d_out, int out_size)
{
    const float* values = (const float*)d_in[0];
    const int*   labels = (const int*)d_in[1];
    const int N = in_sizes[1];        // 200000
    const int ntiles = N / TILE;      // 1562 (remainder 64 via atomic path)

    const int dyn_bytes = (2 * STG_F + ACC_F) * (int)sizeof(float)
                        + 2 * TILE * (int)sizeof(int);   // 95744 B
    cudaFuncSetAttribute(pool_kernel,
                         cudaFuncAttributeMaxDynamicSharedMemorySize,
                         dyn_bytes);

    pool_kernel<<<2 * NSTREAM, NTHR, dyn_bytes>>>(values, labels,
                                                  (float*)d_out, N, ntiles);
}